// round 2
// baseline (speedup 1.0000x reference)
#include <cuda_runtime.h>
#include <math.h>

#define NN 10000
#define NE 160000
#define DI 128
#define DE 512
#define DH 256

// ---------------- scratch (device globals; no allocation allowed) ----------
__device__ float g_xl[NN * DE];
__device__ float g_xr[NN * DE];
__device__ float g_h[NN * DE];
__device__ float g_agg[NN * DE];
__device__ float g_e[NE];
__device__ float g_w[NE];
__device__ float g_nmax[NN];
__device__ float g_den[NN];
__device__ int   g_src[NE];
__device__ int   g_dst[NE];
__device__ float g_m1[NN * DH];
__device__ float g_m2[NN * DH];
__device__ float g_logit[NN];
__device__ int   g_is64;

// ---------------- edge-index dtype detection + decode -----------------------
// If edge_index is int64 (little-endian, values in [0,1e4)), every odd 32-bit
// word is 0. If int32, odd words are random node ids -> OR is nonzero w.h.p.
__global__ void k_detect(const int* __restrict__ w) {
    __shared__ int s;
    if (threadIdx.x == 0) s = 0;
    __syncthreads();
    int acc = 0;
    for (int i = threadIdx.x; i < 2048; i += 256) acc |= w[2 * i + 1];
    atomicOr(&s, acc);
    __syncthreads();
    if (threadIdx.x == 0) g_is64 = (s == 0) ? 1 : 0;
}

__global__ void k_edges(const int* __restrict__ w) {
    int i = blockIdx.x * blockDim.x + threadIdx.x;
    if (i >= NE) return;
    int s, d;
    if (g_is64) {
        s = w[2 * i];
        d = w[2 * (NE + i)];
    } else {
        s = w[i];
        d = w[NE + i];
    }
    if ((unsigned)s >= NN) s = 0;   // hard safety net
    if ((unsigned)d >= NN) d = 0;
    g_src[i] = s;
    g_dst[i] = d;
}

__global__ void k_init_nodes() {
    int i = blockIdx.x * blockDim.x + threadIdx.x;
    if (i < NN) {
        g_nmax[i] = -3.0e38f;
        g_den[i]  = 0.0f;
    }
}

__global__ void k_zero(float* __restrict__ p, int n) {
    int i = blockIdx.x * blockDim.x + threadIdx.x;
    if (i < n) p[i] = 0.0f;
}

// ---------------- fp32 tiled GEMM: C[N,M] = A[N,K] @ B[K,M] ----------------
// K % 16 == 0, M % 64 == 0 required (holds: K in {128,256,512}, M in {512,256}).
#define BM 64
#define BN 64
#define BK 16
__global__ void k_gemm(const float* __restrict__ A, const float* __restrict__ B,
                       float* __restrict__ C, int N, int K, int M) {
    __shared__ float As[BK][BM];
    __shared__ float Bs[BK][BN];
    int tid = threadIdx.x;
    int tx = tid & 15;
    int ty = tid >> 4;
    int row0 = blockIdx.y * BM;
    int col0 = blockIdx.x * BN;

    int ar = tid >> 2;          // 0..63 : row within A tile
    int ak = (tid & 3) * 4;     // 0,4,8,12 : k offset (float4)
    int bk = tid >> 4;          // 0..15 : k row within B tile
    int bc = (tid & 15) * 4;    // col offset (float4)

    float acc[4][4] = {};

    for (int k0 = 0; k0 < K; k0 += BK) {
        float4 av = make_float4(0.f, 0.f, 0.f, 0.f);
        int grow = row0 + ar;
        if (grow < N)
            av = *(const float4*)(A + (size_t)grow * K + k0 + ak);
        As[ak + 0][ar] = av.x;
        As[ak + 1][ar] = av.y;
        As[ak + 2][ar] = av.z;
        As[ak + 3][ar] = av.w;

        float4 bv = *(const float4*)(B + (size_t)(k0 + bk) * M + col0 + bc);
        *(float4*)&Bs[bk][bc] = bv;
        __syncthreads();

        #pragma unroll
        for (int kk = 0; kk < BK; kk++) {
            float a[4], b[4];
            #pragma unroll
            for (int i = 0; i < 4; i++) a[i] = As[kk][ty * 4 + i];
            #pragma unroll
            for (int j = 0; j < 4; j++) b[j] = Bs[kk][tx * 4 + j];
            #pragma unroll
            for (int i = 0; i < 4; i++)
                #pragma unroll
                for (int j = 0; j < 4; j++)
                    acc[i][j] += a[i] * b[j];
        }
        __syncthreads();
    }

    #pragma unroll
    for (int i = 0; i < 4; i++) {
        int r = row0 + ty * 4 + i;
        if (r >= N) break;
        #pragma unroll
        for (int j = 0; j < 4; j++)
            C[(size_t)r * M + col0 + tx * 4 + j] = acc[i][j];
    }
}

// ---------------- GATv2 edge kernels ---------------------------------------
__device__ __forceinline__ void atomicMaxF(float* addr, float val) {
    int old = __float_as_int(*addr);
    while (__int_as_float(old) < val) {
        int prev = atomicCAS((int*)addr, old, __float_as_int(val));
        if (prev == old) break;
        old = prev;
    }
}

// one warp per edge: e = att . leaky_relu(xl[src] + xr[dst], 0.2)
__global__ void k_edge_att(const float* __restrict__ att) {
    int gt = blockIdx.x * blockDim.x + threadIdx.x;
    int edge = gt >> 5;
    int lane = gt & 31;
    if (edge >= NE) return;
    int s = g_src[edge], d = g_dst[edge];
    const float* ps = g_xl + (size_t)s * DE;
    const float* pd = g_xr + (size_t)d * DE;
    float acc = 0.f;
    #pragma unroll
    for (int i = 0; i < DE / 32; i++) {
        int k = i * 32 + lane;
        float v = ps[k] + pd[k];
        v = (v > 0.f) ? v : 0.2f * v;
        acc += v * att[k];
    }
    #pragma unroll
    for (int o = 16; o; o >>= 1) acc += __shfl_xor_sync(0xffffffffu, acc, o);
    if (lane == 0) {
        g_e[edge] = acc;
        atomicMaxF(&g_nmax[d], acc);
    }
}

// one thread per edge: w = exp(e - max[dst]); atomicAdd denom[dst]
__global__ void k_edge_w() {
    int i = blockIdx.x * blockDim.x + threadIdx.x;
    if (i >= NE) return;
    int d = g_dst[i];
    float w = expf(g_e[i] - g_nmax[d]);
    g_w[i] = w;
    atomicAdd(&g_den[d], w);
}

// one warp per edge: agg[dst] += alpha * xl[src]
__global__ void k_edge_agg() {
    int gt = blockIdx.x * blockDim.x + threadIdx.x;
    int edge = gt >> 5;
    int lane = gt & 31;
    if (edge >= NE) return;
    int s = g_src[edge], d = g_dst[edge];
    float alpha = g_w[edge] / (g_den[d] + 1e-16f);
    const float* ps = g_xl + (size_t)s * DE;
    float* pa = g_agg + (size_t)d * DE;
    #pragma unroll
    for (int i = 0; i < DE / 32; i++) {
        int k = i * 32 + lane;
        atomicAdd(&pa[k], alpha * ps[k]);
    }
}

// h = tanh(agg + bias)
__global__ void k_finish(const float* __restrict__ bias) {
    int i = blockIdx.x * blockDim.x + threadIdx.x;
    if (i < NN * DE) {
        g_h[i] = tanhf(g_agg[i] + bias[i % DE]);
    }
}

// ---------------- MLP kernels ----------------------------------------------
__global__ void k_bias_leaky(float* __restrict__ p, const float* __restrict__ c) {
    int i = blockIdx.x * blockDim.x + threadIdx.x;
    if (i < NN * DH) {
        float v = p[i] + c[i % DH];
        p[i] = (v > 0.f) ? v : 0.1f * v;
    }
}

// logits[n] = m2[n,:] . A3 + c3  (one warp per node)
__global__ void k_dot3(const float* __restrict__ A3, const float* __restrict__ c3) {
    int gt = blockIdx.x * blockDim.x + threadIdx.x;
    int n = gt >> 5;
    int lane = gt & 31;
    if (n >= NN) return;
    const float* pm = g_m2 + (size_t)n * DH;
    float acc = 0.f;
    #pragma unroll
    for (int i = 0; i < DH / 32; i++) {
        int k = i * 32 + lane;
        acc += pm[k] * A3[k];
    }
    #pragma unroll
    for (int o = 16; o; o >>= 1) acc += __shfl_xor_sync(0xffffffffu, acc, o);
    if (lane == 0) g_logit[n] = acc + c3[0];
}

// softmax over all NN logits (single block)
__global__ void k_softmax(float* __restrict__ out) {
    __shared__ float sh[1024];
    int t = threadIdx.x;
    float m = -3.0e38f;
    for (int i = t; i < NN; i += 1024) m = fmaxf(m, g_logit[i]);
    sh[t] = m; __syncthreads();
    for (int s = 512; s; s >>= 1) { if (t < s) sh[t] = fmaxf(sh[t], sh[t + s]); __syncthreads(); }
    float gm = sh[0]; __syncthreads();
    float sum = 0.f;
    for (int i = t; i < NN; i += 1024) sum += expf(g_logit[i] - gm);
    sh[t] = sum; __syncthreads();
    for (int s = 512; s; s >>= 1) { if (t < s) sh[t] += sh[t + s]; __syncthreads(); }
    float gs = sh[0];
    for (int i = t; i < NN; i += 1024) out[i] = expf(g_logit[i] - gm) / gs;
}

// ---------------- host side -------------------------------------------------
static void gat_layer(const float* hin, int din,
                      const float* Wl, const float* Wr,
                      const float* att, const float* bias,
                      float* xl, float* xr, float* agg) {
    dim3 gg(DE / BN, (NN + BM - 1) / BM);
    k_gemm<<<gg, 256>>>(hin, Wl, xl, NN, din, DE);
    k_gemm<<<gg, 256>>>(hin, Wr, xr, NN, din, DE);
    k_init_nodes<<<(NN + 255) / 256, 256>>>();
    k_zero<<<(NN * DE + 255) / 256, 256>>>(agg, NN * DE);
    k_edge_att<<<(NE * 32 + 255) / 256, 256>>>(att);
    k_edge_w<<<(NE + 255) / 256, 256>>>();
    k_edge_agg<<<(NE * 32 + 255) / 256, 256>>>();
    k_finish<<<(NN * DE + 255) / 256, 256>>>(bias);
}

extern "C" void kernel_launch(void* const* d_in, const int* in_sizes, int n_in,
                              void* d_out, int out_size) {
    const float* x   = (const float*)d_in[0];
    const int*   ei  = (const int*)d_in[1];   // int32 or int64 words; detected on-device
    const float* Wl1 = (const float*)d_in[2];
    const float* Wr1 = (const float*)d_in[3];
    const float* at1 = (const float*)d_in[4];
    const float* b1  = (const float*)d_in[5];
    const float* Wl2 = (const float*)d_in[6];
    const float* Wr2 = (const float*)d_in[7];
    const float* at2 = (const float*)d_in[8];
    const float* b2  = (const float*)d_in[9];
    const float* Wl3 = (const float*)d_in[10];
    const float* Wr3 = (const float*)d_in[11];
    const float* at3 = (const float*)d_in[12];
    const float* b3  = (const float*)d_in[13];
    const float* A1  = (const float*)d_in[14];
    const float* c1  = (const float*)d_in[15];
    const float* A2  = (const float*)d_in[16];
    const float* c2  = (const float*)d_in[17];
    const float* A3  = (const float*)d_in[18];
    const float* c3  = (const float*)d_in[19];
    float* out = (float*)d_out;

    float *xl, *xr, *h, *agg, *m1, *m2;
    cudaGetSymbolAddress((void**)&xl,  g_xl);
    cudaGetSymbolAddress((void**)&xr,  g_xr);
    cudaGetSymbolAddress((void**)&h,   g_h);
    cudaGetSymbolAddress((void**)&agg, g_agg);
    cudaGetSymbolAddress((void**)&m1,  g_m1);
    cudaGetSymbolAddress((void**)&m2,  g_m2);

    k_detect<<<1, 256>>>(ei);
    k_edges<<<(NE + 255) / 256, 256>>>(ei);

    gat_layer(x, DI, Wl1, Wr1, at1, b1, xl, xr, agg);
    gat_layer(h, DE, Wl2, Wr2, at2, b2, xl, xr, agg);
    gat_layer(h, DE, Wl3, Wr3, at3, b3, xl, xr, agg);

    // MLP
    {
        dim3 g1(DH / BN, (NN + BM - 1) / BM);
        k_gemm<<<g1, 256>>>(h, A1, m1, NN, DE, DH);
        k_bias_leaky<<<(NN * DH + 255) / 256, 256>>>(m1, c1);
        k_gemm<<<g1, 256>>>(m1, A2, m2, NN, DH, DH);
        k_bias_leaky<<<(NN * DH + 255) / 256, 256>>>(m2, c2);
        k_dot3<<<(NN * 32 + 255) / 256, 256>>>(A3, c3);
        k_softmax<<<1, 1024>>>(out);
    }
}